// round 1
// baseline (speedup 1.0000x reference)
#include <cuda_runtime.h>
#include <math.h>

#define NB 16
#define NT 32
#define HH 40
#define WW 40
#define FF 40
#define GATES 160   // 4*FF

// ---------------- scratch (no allocations allowed) ----------------
__device__ float g_seqA[(size_t)NB*NT*HH*WW*FF];   // 131 MB
__device__ float g_seqB[(size_t)NB*NT*HH*WW*FF];   // 131 MB
__device__ float g_hA[NB*HH*WW*FF];
__device__ float g_hB[NB*HH*WW*FF];
__device__ float g_c [NB*HH*WW*FF];

__global__ void zero_kernel(float* __restrict__ p, int n) {
    int i = blockIdx.x * blockDim.x + threadIdx.x;
    if (i < n) p[i] = 0.f;
}

__device__ __forceinline__ float hsig(float x) {
    return fminf(fmaxf(0.2f * x + 0.5f, 0.f), 1.f);
}

// ---------------- fused ConvLSTM step + BN epilogue ----------------
// Block: one (batch b, output row) strip: 40 pixels x all 160 gate channels.
// blockDim = (40, 10). Thread (w, ty) computes f-channels jb..jb+3 (jb=ty*4)
// for all 4 gates (16 fp32 accumulators).
template <int CIN>
__global__ __launch_bounds__(400, 2)
void lstm_step_kernel(
    const float* __restrict__ x_t, int bstride_x,     // x_t + b*bstride_x -> [H][W][CIN]
    const float* __restrict__ h_prev,                 // [B][H][W][FF]
    float*       __restrict__ h_next,                 // [B][H][W][FF]
    float*       __restrict__ c_buf,                  // [B][H][W][FF]
    float*       __restrict__ out_t, int bstride_o,   // out_t + b*bstride_o -> [H][W][FF]
    const float* __restrict__ Wx,                     // [3][3][CIN][160]
    const float* __restrict__ Wh,                     // [3][3][FF][160]
    const float* __restrict__ bias,                   // [160]
    const float* __restrict__ gam,
    const float* __restrict__ bet,
    const float* __restrict__ mu,
    const float* __restrict__ var)
{
    __shared__ __align__(16) float xs[CIN * 3 * 42];  // [c][dy][col], col = w+1 (halo)
    __shared__ __align__(16) float hs[FF  * 3 * 42];

    const int w   = threadIdx.x;   // 0..39
    const int ty  = threadIdx.y;   // 0..9
    const int row = blockIdx.x;    // 0..39
    const int b   = blockIdx.y;    // 0..15
    const int tid = ty * 40 + w;

    const float* xb = x_t   + (size_t)b * bstride_x;
    const float* hb = h_prev + (size_t)b * (HH * WW * FF);

    // tile loads (zero-padded halo), layout index i = c*126 + dy*42 + col
    for (int i = tid; i < CIN * 126; i += 400) {
        int c = i / 126, r = i % 126, dy = r / 42, col = r % 42;
        int rr = row + dy - 1, cc = col - 1;
        float v = 0.f;
        if ((unsigned)rr < HH && (unsigned)cc < WW) v = xb[(rr * WW + cc) * CIN + c];
        xs[i] = v;
    }
    for (int i = tid; i < FF * 126; i += 400) {
        int c = i / 126, r = i % 126, dy = r / 42, col = r % 42;
        int rr = row + dy - 1, cc = col - 1;
        float v = 0.f;
        if ((unsigned)rr < HH && (unsigned)cc < WW) v = hb[(rr * WW + cc) * FF + c];
        hs[i] = v;
    }
    __syncthreads();

    const int jb = ty * 4;
    float4 ai = *(const float4*)(bias + 0 * FF + jb);
    float4 af = *(const float4*)(bias + 1 * FF + jb);
    float4 ag = *(const float4*)(bias + 2 * FF + jb);
    float4 ao = *(const float4*)(bias + 3 * FF + jb);

#define ACC16(V, WI, WF, WG, WO)                                           \
    ai.x += (V)*(WI).x; ai.y += (V)*(WI).y; ai.z += (V)*(WI).z; ai.w += (V)*(WI).w; \
    af.x += (V)*(WF).x; af.y += (V)*(WF).y; af.z += (V)*(WF).z; af.w += (V)*(WF).w; \
    ag.x += (V)*(WG).x; ag.y += (V)*(WG).y; ag.z += (V)*(WG).z; ag.w += (V)*(WG).w; \
    ao.x += (V)*(WO).x; ao.y += (V)*(WO).y; ao.z += (V)*(WO).z; ao.w += (V)*(WO).w;

#pragma unroll
    for (int dy = 0; dy < 3; dy++) {
#pragma unroll
        for (int dw = 0; dw < 3; dw++) {
            const int k = dy * 3 + dw;
            {   // x-conv
                const float* wk = Wx + (size_t)k * CIN * GATES;
                const float* xp = xs + dy * 42 + w + dw;
#pragma unroll 4
                for (int c = 0; c < CIN; c++) {
                    float xv = xp[c * 126];
                    const float4* wr = (const float4*)(wk + (size_t)c * GATES);
                    float4 wi = wr[ 0 + ty];
                    float4 wf = wr[10 + ty];
                    float4 wg = wr[20 + ty];
                    float4 wo = wr[30 + ty];
                    ACC16(xv, wi, wf, wg, wo)
                }
            }
            {   // h-conv
                const float* wk = Wh + (size_t)k * FF * GATES;
                const float* hp = hs + dy * 42 + w + dw;
#pragma unroll 4
                for (int c = 0; c < FF; c++) {
                    float hv = hp[c * 126];
                    const float4* wr = (const float4*)(wk + (size_t)c * GATES);
                    float4 wi = wr[ 0 + ty];
                    float4 wf = wr[10 + ty];
                    float4 wg = wr[20 + ty];
                    float4 wo = wr[30 + ty];
                    ACC16(hv, wi, wf, wg, wo)
                }
            }
        }
    }
#undef ACC16

    // ---- epilogue: cell update + BN ----
    const int pix = (b * HH + row) * WW + w;
    float4* cp = (float4*)(c_buf + (size_t)pix * FF + jb);
    float4 cv = *cp;
    float4 hn, ob;

    float zi[4] = {ai.x, ai.y, ai.z, ai.w};
    float zf[4] = {af.x, af.y, af.z, af.w};
    float zg[4] = {ag.x, ag.y, ag.z, ag.w};
    float zo[4] = {ao.x, ao.y, ao.z, ao.w};
    float cc4[4] = {cv.x, cv.y, cv.z, cv.w};
    float hh4[4], oo4[4];

#pragma unroll
    for (int q = 0; q < 4; q++) {
        float cn = hsig(zf[q]) * cc4[q] + hsig(zi[q]) * tanhf(zg[q]);
        cc4[q] = cn;
        float h = hsig(zo[q]) * tanhf(cn);
        hh4[q] = h;
        int f = jb + q;
        float sc = gam[f] * rsqrtf(var[f] + 1e-3f);
        oo4[q] = (h - mu[f]) * sc + bet[f];
    }
    cv.x = cc4[0]; cv.y = cc4[1]; cv.z = cc4[2]; cv.w = cc4[3];
    hn.x = hh4[0]; hn.y = hh4[1]; hn.z = hh4[2]; hn.w = hh4[3];
    ob.x = oo4[0]; ob.y = oo4[1]; ob.z = oo4[2]; ob.w = oo4[3];

    *cp = cv;
    *(float4*)(h_next + (size_t)pix * FF + jb) = hn;
    *(float4*)(out_t + (size_t)b * bstride_o + (size_t)(row * WW + w) * FF + jb) = ob;
}

// ---------------- final Conv3D (3x3x3 over T,H,W) + sigmoid ----------------
__global__ __launch_bounds__(320)
void conv3d_kernel(const float* __restrict__ in,    // [B][T][H][W][FF]
                   const float* __restrict__ W3,    // [3][3][3][FF]
                   const float* __restrict__ b3,
                   float* __restrict__ out)         // [B][T][H][W]
{
    __shared__ __align__(16) float ws[27 * FF];
    int tid = threadIdx.y * 40 + threadIdx.x;
    for (int i = tid; i < 27 * FF; i += 320) ws[i] = W3[i];
    __syncthreads();

    const int w   = threadIdx.x;
    const int t   = blockIdx.x * 8 + threadIdx.y;
    const int row = blockIdx.y;
    const int b   = blockIdx.z;

    float acc = b3[0];
#pragma unroll
    for (int dt = 0; dt < 3; dt++) {
        int tt = t + dt - 1;
        if ((unsigned)tt >= NT) continue;
#pragma unroll
        for (int dh = 0; dh < 3; dh++) {
            int rr = row + dh - 1;
            if ((unsigned)rr >= HH) continue;
            const float* rp = in + ((size_t)(b * NT + tt) * HH + rr) * WW * FF;
#pragma unroll
            for (int dw = 0; dw < 3; dw++) {
                int cc = w + dw - 1;
                if ((unsigned)cc >= WW) continue;
                const float4* pp = (const float4*)(rp + (size_t)cc * FF);
                const float*  wp = ws + ((dt * 3 + dh) * 3 + dw) * FF;
#pragma unroll
                for (int q = 0; q < 10; q++) {
                    float4 v  = pp[q];
                    float4 wv = *(const float4*)(wp + q * 4);
                    acc += v.x * wv.x + v.y * wv.y + v.z * wv.z + v.w * wv.w;
                }
            }
        }
    }
    out[((size_t)(b * NT + t) * HH + row) * WW + w] = 1.f / (1.f + expf(-acc));
}

// ---------------- launch ----------------
extern "C" void kernel_launch(void* const* d_in, const int* in_sizes, int n_in,
                              void* d_out, int out_size)
{
    (void)in_sizes; (void)n_in; (void)out_size;
    const float* inputs = (const float*)d_in[0];

    struct LayerP { const float *Wx, *Wh, *b, *g, *be, *mu, *v; };
    LayerP L[4];
    for (int l = 0; l < 4; l++) {
        int base = 1 + 7 * l;
        L[l].Wx = (const float*)d_in[base + 0];
        L[l].Wh = (const float*)d_in[base + 1];
        L[l].b  = (const float*)d_in[base + 2];
        L[l].g  = (const float*)d_in[base + 3];
        L[l].be = (const float*)d_in[base + 4];
        L[l].mu = (const float*)d_in[base + 5];
        L[l].v  = (const float*)d_in[base + 6];
    }
    const float* W3 = (const float*)d_in[29];
    const float* b3 = (const float*)d_in[30];

    float *seqA, *seqB, *hA, *hB, *cbuf;
    cudaGetSymbolAddress((void**)&seqA, g_seqA);
    cudaGetSymbolAddress((void**)&seqB, g_seqB);
    cudaGetSymbolAddress((void**)&hA,   g_hA);
    cudaGetSymbolAddress((void**)&hB,   g_hB);
    cudaGetSymbolAddress((void**)&cbuf, g_c);

    const dim3 blk(40, 10), grd(HH, NB);
    const int nhc = NB * HH * WW * FF;

    const float* in_base = inputs;
    int cin = 1;
    float* out_base = seqA;

    for (int l = 0; l < 4; l++) {
        zero_kernel<<<(nhc + 255) / 256, 256>>>(hA, nhc);
        zero_kernel<<<(nhc + 255) / 256, 256>>>(cbuf, nhc);
        float* hc = hA;
        float* hn = hB;
        const int bsx = NT * HH * WW * cin;
        const int bso = NT * HH * WW * FF;
        for (int t = 0; t < NT; t++) {
            const float* xt = in_base + (size_t)t * HH * WW * cin;
            float* ot = out_base + (size_t)t * HH * WW * FF;
            if (cin == 1) {
                lstm_step_kernel<1><<<grd, blk>>>(xt, bsx, hc, hn, cbuf, ot, bso,
                                                  L[l].Wx, L[l].Wh, L[l].b,
                                                  L[l].g, L[l].be, L[l].mu, L[l].v);
            } else {
                lstm_step_kernel<40><<<grd, blk>>>(xt, bsx, hc, hn, cbuf, ot, bso,
                                                   L[l].Wx, L[l].Wh, L[l].b,
                                                   L[l].g, L[l].be, L[l].mu, L[l].v);
            }
            float* tmp = hc; hc = hn; hn = tmp;
        }
        in_base = out_base;
        cin = FF;
        out_base = (out_base == seqA) ? seqB : seqA;
    }

    conv3d_kernel<<<dim3(4, HH, NB), dim3(40, 8)>>>(in_base, W3, b3, (float*)d_out);
}

// round 2
// speedup vs baseline: 1.6048x; 1.6048x over previous
#include <cuda_runtime.h>
#include <math.h>

#define NB 16
#define NT 32
#define HH 40
#define WW 40
#define FF 40
#define GATES 160   // 4*FF

typedef unsigned long long ull;

// ---------------- scratch (no allocations allowed) ----------------
__device__ float g_seqA[(size_t)NB*NT*HH*WW*FF];   // 131 MB
__device__ float g_seqB[(size_t)NB*NT*HH*WW*FF];   // 131 MB
__device__ float g_hA[NB*HH*WW*FF];
__device__ float g_hB[NB*HH*WW*FF];
__device__ float g_c [NB*HH*WW*FF];

__global__ void zero_kernel(float* __restrict__ p, int n) {
    int i = blockIdx.x * blockDim.x + threadIdx.x;
    if (i < n) p[i] = 0.f;
}

__device__ __forceinline__ float hsig(float x) {
    return fminf(fmaxf(0.2f * x + 0.5f, 0.f), 1.f);
}
__device__ __forceinline__ ull pack2(float v) {
    ull r; asm("mov.b64 %0, {%1, %1};" : "=l"(r) : "f"(v)); return r;
}
__device__ __forceinline__ void ffma2(ull& d, ull a, ull b) {
    asm("fma.rn.f32x2 %0, %1, %2, %0;" : "+l"(d) : "l"(a), "l"(b));
}
__device__ __forceinline__ float2 unpk(ull v) {
    float lo, hi; asm("mov.b64 {%0, %1}, %2;" : "=f"(lo), "=f"(hi) : "l"(v));
    return make_float2(lo, hi);
}

// ---------------- fused ConvLSTM step + BN epilogue ----------------
// Block: one (batch b, output row): 40 pixels x 160 gate channels.
// blockDim = (20, 10). Thread (tx, ty): pixels w=tx and w=tx+20,
// f-channels jb..jb+3 (jb=ty*4) for all 4 gates.
// Accumulators are f32x2 pairs: A[p][0..7] = {i01,i23,f01,f23,g01,g23,o01,o23}.
template <int CIN>
__global__ __launch_bounds__(200)
void lstm_step_kernel(
    const float* __restrict__ x_t, int bstride_x,     // x_t + b*bstride_x -> [H][W][CIN]
    const float* __restrict__ h_prev,                 // [B][H][W][FF]
    float*       __restrict__ h_next,                 // [B][H][W][FF]
    float*       __restrict__ c_buf,                  // [B][H][W][FF]
    float*       __restrict__ out_t, int bstride_o,   // out_t + b*bstride_o -> [H][W][FF]
    const float* __restrict__ Wx,                     // [3][3][CIN][160]
    const float* __restrict__ Wh,                     // [3][3][FF][160]
    const float* __restrict__ bias,                   // [160]
    const float* __restrict__ gam,
    const float* __restrict__ bet,
    const float* __restrict__ mu,
    const float* __restrict__ var)
{
    // [c][j] with j = dy*42 + col (col = w+1 halo), row stride padded to 127
    __shared__ __align__(16) float xs[CIN * 127];
    __shared__ __align__(16) float hs[FF  * 127];

    const int tx  = threadIdx.x;   // 0..19
    const int ty  = threadIdx.y;   // 0..9
    const int row = blockIdx.x;    // 0..39
    const int b   = blockIdx.y;    // 0..15
    const int tid = ty * 20 + tx;

    const float* xb = x_t    + (size_t)b * bstride_x;
    const float* hb = h_prev + (size_t)b * (HH * WW * FF);

    // tile loads: c fastest for coalescing; smem write stride 127 (conflict-free)
    for (int i = tid; i < CIN * 126; i += 200) {
        int c = i % CIN, j = i / CIN;
        int dy = j / 42, col = j % 42;
        int rr = row + dy - 1, cc = col - 1;
        float v = 0.f;
        if ((unsigned)rr < HH && (unsigned)cc < WW) v = xb[(rr * WW + cc) * CIN + c];
        xs[c * 127 + j] = v;
    }
    for (int i = tid; i < FF * 126; i += 200) {
        int c = i % FF, j = i / FF;
        int dy = j / 42, col = j % 42;
        int rr = row + dy - 1, cc = col - 1;
        float v = 0.f;
        if ((unsigned)rr < HH && (unsigned)cc < WW) v = hb[(rr * WW + cc) * FF + c];
        hs[c * 127 + j] = v;
    }
    __syncthreads();

    const int jb = ty * 4;
    ull A[2][8];
    {
        ulonglong2 bi = *(const ulonglong2*)(bias + 0 * FF + jb);
        ulonglong2 bf = *(const ulonglong2*)(bias + 1 * FF + jb);
        ulonglong2 bg = *(const ulonglong2*)(bias + 2 * FF + jb);
        ulonglong2 bo = *(const ulonglong2*)(bias + 3 * FF + jb);
        A[0][0] = A[1][0] = bi.x;  A[0][1] = A[1][1] = bi.y;
        A[0][2] = A[1][2] = bf.x;  A[0][3] = A[1][3] = bf.y;
        A[0][4] = A[1][4] = bg.x;  A[0][5] = A[1][5] = bg.y;
        A[0][6] = A[1][6] = bo.x;  A[0][7] = A[1][7] = bo.y;
    }

#define STEP16(P, V, WI, WF, WG, WO)            \
    ffma2(A[P][0], V, (WI).x); ffma2(A[P][1], V, (WI).y); \
    ffma2(A[P][2], V, (WF).x); ffma2(A[P][3], V, (WF).y); \
    ffma2(A[P][4], V, (WG).x); ffma2(A[P][5], V, (WG).y); \
    ffma2(A[P][6], V, (WO).x); ffma2(A[P][7], V, (WO).y);

#pragma unroll 1
    for (int dy = 0; dy < 3; dy++) {
#pragma unroll 1
        for (int dw = 0; dw < 3; dw++) {
            const int k = dy * 3 + dw;
            {   // x-conv contribution
                const float* wk = Wx + (size_t)k * CIN * GATES + jb;
                const float* p0 = xs + dy * 42 + tx + dw;
                const float* p1 = p0 + 20;
#pragma unroll 4
                for (int c = 0; c < CIN; c++) {
                    const float* wc = wk + c * GATES;
                    ulonglong2 wi = *(const ulonglong2*)(wc);
                    ulonglong2 wf = *(const ulonglong2*)(wc + FF);
                    ulonglong2 wg = *(const ulonglong2*)(wc + 2 * FF);
                    ulonglong2 wo = *(const ulonglong2*)(wc + 3 * FF);
                    ull v0 = pack2(p0[c * 127]);
                    ull v1 = pack2(p1[c * 127]);
                    STEP16(0, v0, wi, wf, wg, wo)
                    STEP16(1, v1, wi, wf, wg, wo)
                }
            }
            {   // h-conv contribution
                const float* wk = Wh + (size_t)k * FF * GATES + jb;
                const float* p0 = hs + dy * 42 + tx + dw;
                const float* p1 = p0 + 20;
#pragma unroll 4
                for (int c = 0; c < FF; c++) {
                    const float* wc = wk + c * GATES;
                    ulonglong2 wi = *(const ulonglong2*)(wc);
                    ulonglong2 wf = *(const ulonglong2*)(wc + FF);
                    ulonglong2 wg = *(const ulonglong2*)(wc + 2 * FF);
                    ulonglong2 wo = *(const ulonglong2*)(wc + 3 * FF);
                    ull v0 = pack2(p0[c * 127]);
                    ull v1 = pack2(p1[c * 127]);
                    STEP16(0, v0, wi, wf, wg, wo)
                    STEP16(1, v1, wi, wf, wg, wo)
                }
            }
        }
    }
#undef STEP16

    // ---- epilogue: cell update + BN, for both pixels ----
    const int pixrow = (b * HH + row) * WW;
#pragma unroll
    for (int p = 0; p < 2; p++) {
        const int w = tx + 20 * p;
        const int pix = pixrow + w;
        float z[16];
#pragma unroll
        for (int q = 0; q < 8; q++) {
            float2 t = unpk(A[p][q]);
            z[q * 2] = t.x; z[q * 2 + 1] = t.y;
        }
        // z[0..3]=i, z[4..7]=f, z[8..11]=g, z[12..15]=o  (channels jb..jb+3)
        float4* cp = (float4*)(c_buf + (size_t)pix * FF + jb);
        float4 cv = *cp;
        float cc4[4] = {cv.x, cv.y, cv.z, cv.w};
        float hh4[4], oo4[4];
#pragma unroll
        for (int q = 0; q < 4; q++) {
            float cn = hsig(z[4 + q]) * cc4[q] + hsig(z[q]) * tanhf(z[8 + q]);
            cc4[q] = cn;
            float h = hsig(z[12 + q]) * tanhf(cn);
            hh4[q] = h;
            int f = jb + q;
            float sc = gam[f] * rsqrtf(var[f] + 1e-3f);
            oo4[q] = (h - mu[f]) * sc + bet[f];
        }
        float4 cn4 = make_float4(cc4[0], cc4[1], cc4[2], cc4[3]);
        float4 hn4 = make_float4(hh4[0], hh4[1], hh4[2], hh4[3]);
        float4 ob4 = make_float4(oo4[0], oo4[1], oo4[2], oo4[3]);
        *cp = cn4;
        *(float4*)(h_next + (size_t)pix * FF + jb) = hn4;
        *(float4*)(out_t + (size_t)b * bstride_o + (size_t)(row * WW + w) * FF + jb) = ob4;
    }
}

// ---------------- final Conv3D (3x3x3 over T,H,W) + sigmoid ----------------
__global__ __launch_bounds__(320)
void conv3d_kernel(const float* __restrict__ in,    // [B][T][H][W][FF]
                   const float* __restrict__ W3,    // [3][3][3][FF]
                   const float* __restrict__ b3,
                   float* __restrict__ out)         // [B][T][H][W]
{
    __shared__ __align__(16) float ws[27 * FF];
    int tid = threadIdx.y * 40 + threadIdx.x;
    for (int i = tid; i < 27 * FF; i += 320) ws[i] = W3[i];
    __syncthreads();

    const int w   = threadIdx.x;
    const int t   = blockIdx.x * 8 + threadIdx.y;
    const int row = blockIdx.y;
    const int b   = blockIdx.z;

    float acc = b3[0];
#pragma unroll
    for (int dt = 0; dt < 3; dt++) {
        int tt = t + dt - 1;
        if ((unsigned)tt >= NT) continue;
#pragma unroll
        for (int dh = 0; dh < 3; dh++) {
            int rr = row + dh - 1;
            if ((unsigned)rr >= HH) continue;
            const float* rp = in + ((size_t)(b * NT + tt) * HH + rr) * WW * FF;
#pragma unroll
            for (int dw = 0; dw < 3; dw++) {
                int cc = w + dw - 1;
                if ((unsigned)cc >= WW) continue;
                const float4* pp = (const float4*)(rp + (size_t)cc * FF);
                const float*  wp = ws + ((dt * 3 + dh) * 3 + dw) * FF;
#pragma unroll
                for (int q = 0; q < 10; q++) {
                    float4 v  = pp[q];
                    float4 wv = *(const float4*)(wp + q * 4);
                    acc += v.x * wv.x + v.y * wv.y + v.z * wv.z + v.w * wv.w;
                }
            }
        }
    }
    out[((size_t)(b * NT + t) * HH + row) * WW + w] = 1.f / (1.f + expf(-acc));
}

// ---------------- launch ----------------
extern "C" void kernel_launch(void* const* d_in, const int* in_sizes, int n_in,
                              void* d_out, int out_size)
{
    (void)in_sizes; (void)n_in; (void)out_size;
    const float* inputs = (const float*)d_in[0];

    struct LayerP { const float *Wx, *Wh, *b, *g, *be, *mu, *v; };
    LayerP L[4];
    for (int l = 0; l < 4; l++) {
        int base = 1 + 7 * l;
        L[l].Wx = (const float*)d_in[base + 0];
        L[l].Wh = (const float*)d_in[base + 1];
        L[l].b  = (const float*)d_in[base + 2];
        L[l].g  = (const float*)d_in[base + 3];
        L[l].be = (const float*)d_in[base + 4];
        L[l].mu = (const float*)d_in[base + 5];
        L[l].v  = (const float*)d_in[base + 6];
    }
    const float* W3 = (const float*)d_in[29];
    const float* b3 = (const float*)d_in[30];

    float *seqA, *seqB, *hA, *hB, *cbuf;
    cudaGetSymbolAddress((void**)&seqA, g_seqA);
    cudaGetSymbolAddress((void**)&seqB, g_seqB);
    cudaGetSymbolAddress((void**)&hA,   g_hA);
    cudaGetSymbolAddress((void**)&hB,   g_hB);
    cudaGetSymbolAddress((void**)&cbuf, g_c);

    const dim3 blk(20, 10), grd(HH, NB);
    const int nhc = NB * HH * WW * FF;

    const float* in_base = inputs;
    int cin = 1;
    float* out_base = seqA;

    for (int l = 0; l < 4; l++) {
        zero_kernel<<<(nhc + 255) / 256, 256>>>(hA, nhc);
        zero_kernel<<<(nhc + 255) / 256, 256>>>(cbuf, nhc);
        float* hc = hA;
        float* hn = hB;
        const int bsx = NT * HH * WW * cin;
        const int bso = NT * HH * WW * FF;
        for (int t = 0; t < NT; t++) {
            const float* xt = in_base + (size_t)t * HH * WW * cin;
            float* ot = out_base + (size_t)t * HH * WW * FF;
            if (cin == 1) {
                lstm_step_kernel<1><<<grd, blk>>>(xt, bsx, hc, hn, cbuf, ot, bso,
                                                  L[l].Wx, L[l].Wh, L[l].b,
                                                  L[l].g, L[l].be, L[l].mu, L[l].v);
            } else {
                lstm_step_kernel<40><<<grd, blk>>>(xt, bsx, hc, hn, cbuf, ot, bso,
                                                   L[l].Wx, L[l].Wh, L[l].b,
                                                   L[l].g, L[l].be, L[l].mu, L[l].v);
            }
            float* tmp = hc; hc = hn; hn = tmp;
        }
        in_base = out_base;
        cin = FF;
        out_base = (out_base == seqA) ? seqB : seqA;
    }

    conv3d_kernel<<<dim3(4, HH, NB), dim3(40, 8)>>>(in_base, W3, b3, (float*)d_out);
}